// round 3
// baseline (speedup 1.0000x reference)
#include <cuda_runtime.h>
#include <cstdint>

typedef unsigned long long ull;

// ---------------- problem constants ----------------
#define BB 32
#define CC 3
#define HH 512
#define WW 512
#define NX 64
#define NY 64
#define KTOT (CC*HH*WW)          // 786432
#define NBLK1 384                // locnet blocks: 384*256*8 = 786432

// ---------------- device scratch (no allocations allowed) ----------------
__device__ float g_partial[160 * NBLK1];      // t-major: [t][g]
__device__ float g_p[BB * 5];
__device__ float g_Fx[BB * NX * WW];          // [b][nx][w]
__device__ float g_Fy[BB * NY * HH];          // [b][ny][h], * gamma
__device__ float g_GxP[2][BB * CC * HH * NX]; // w-split partials [ws][b][c][h][m]

// ---------------- packed f32x2 helpers ----------------
__device__ __forceinline__ ull fma2(ull a, ull b, ull c) {
    ull d;
    asm("fma.rn.f32x2 %0, %1, %2, %3;" : "=l"(d) : "l"(a), "l"(b), "l"(c));
    return d;
}
__device__ __forceinline__ float2 unpack2(ull v) {
    float2 f;
    asm("mov.b64 {%0, %1}, %2;" : "=f"(f.x), "=f"(f.y) : "l"(v));
    return f;
}

// ============================================================================
// K1: locnet partial sums. Block g covers k in [g*2048, (g+1)*2048).
// float4 X loads; W chunk in registers, reused across all 32 batches.
// ============================================================================
__global__ __launch_bounds__(256) void k_locnet(const float* __restrict__ X,
                                                const float* __restrict__ Wl) {
    const int tid = threadIdx.x;
    const int base = blockIdx.x * 2048;

    // W for 2 groups of 4 consecutive k handled by this thread
    float w[2][4][5];
#pragma unroll
    for (int it = 0; it < 2; it++) {
        const int k0 = base + it * 1024 + tid * 4;
#pragma unroll
        for (int q = 0; q < 4; q++)
#pragma unroll
            for (int j = 0; j < 5; j++) w[it][q][j] = Wl[(k0 + q) * 5 + j];
    }

    __shared__ float ps[160];
    if (tid < 160) ps[tid] = 0.0f;
    __syncthreads();

#pragma unroll 2
    for (int b = 0; b < BB; b++) {
        float acc[5] = {0.f, 0.f, 0.f, 0.f, 0.f};
        const float* Xb = X + (size_t)b * KTOT + base;
#pragma unroll
        for (int it = 0; it < 2; it++) {
            const float4 x = *(const float4*)&Xb[it * 1024 + tid * 4];
#pragma unroll
            for (int j = 0; j < 5; j++) {
                acc[j] = fmaf(x.x, w[it][0][j], acc[j]);
                acc[j] = fmaf(x.y, w[it][1][j], acc[j]);
                acc[j] = fmaf(x.z, w[it][2][j], acc[j]);
                acc[j] = fmaf(x.w, w[it][3][j], acc[j]);
            }
        }
#pragma unroll
        for (int j = 0; j < 5; j++) {
            float v = acc[j];
#pragma unroll
            for (int off = 16; off > 0; off >>= 1)
                v += __shfl_down_sync(0xffffffffu, v, off);
            if ((tid & 31) == 0) atomicAdd(&ps[b * 5 + j], v);
        }
    }
    __syncthreads();
    if (tid < 160) g_partial[tid * NBLK1 + blockIdx.x] = ps[tid];  // t-major
}

// K1b: final reduce + bias. One 32-lane block per output t (coalesced).
__global__ __launch_bounds__(32) void k_reduce_p(const float* __restrict__ b_loc) {
    const int t = blockIdx.x;       // 0..159
    const int lane = threadIdx.x;
    const float* src = g_partial + (size_t)t * NBLK1;
    float s = 0.0f;
#pragma unroll
    for (int i = 0; i < NBLK1 / 32; i++) s += src[lane + i * 32];
#pragma unroll
    for (int off = 16; off > 0; off >>= 1)
        s += __shfl_down_sync(0xffffffffu, s, off);
    if (lane == 0) g_p[t] = s + b_loc[t % 5];
}

// ============================================================================
// K2: filter banks. grid (64, 2, 32). gamma folded into Fy.
// ============================================================================
__global__ __launch_bounds__(128) void k_filters() {
    const int n = blockIdx.x;
    const int axis = blockIdx.y;  // 0: Fx (W), 1: Fy (H)
    const int b = blockIdx.z;
    const int tid = threadIdx.x;

    const float* pb = g_p + b * 5;
    const float sigma2 = expf(pb[2]);
    const float delta = expf(pb[3]) * (511.0f / 63.0f);
    const float gctr = (axis == 0) ? 32.0f * (pb[0] + 1.0f) : 32.0f * (pb[1] + 1.0f);
    const float m = gctr + delta * ((float)n - 32.5f);
    const float inv2s = 1.0f / (2.0f * sigma2);

    float vals[4];
    float lsum = 0.0f;
#pragma unroll
    for (int i = 0; i < 4; i++) {
        const float a = (float)(tid + i * 128);
        const float d = a - m;
        const float e = expf(-d * d * inv2s);
        vals[i] = e;
        lsum += e;
    }
    __shared__ float sw[4];
#pragma unroll
    for (int off = 16; off > 0; off >>= 1)
        lsum += __shfl_down_sync(0xffffffffu, lsum, off);
    if ((tid & 31) == 0) sw[tid >> 5] = lsum;
    __syncthreads();
    const float tot = sw[0] + sw[1] + sw[2] + sw[3];
    float scale = 1.0f / (tot + 1e-4f);
    if (axis == 1) scale *= expf(pb[4]);

    float* dst = (axis == 0 ? g_Fx : g_Fy) + ((size_t)b * 64 + n) * 512;
#pragma unroll
    for (int i = 0; i < 4; i++) dst[tid + i * 128] = vals[i] * scale;
}

// ============================================================================
// K3: GxP[ws][b,c,h,m] = sum_{w in half ws} X[b,c,h,w] * Fx[b,m,w]
// Block 128h x 64m over 256 w. 128 threads, thread tile 8h x 8m.
// f32x2 acc over h-pairs; x via direct LDS.128, f via duplicated LDS.128.
// Inner loop per w: 6 LDS.128 + 32 FFMA2, zero pack MOVs.
// grid (8 = 4 htiles * 2 wsplits, 3 c, 32 b) = 768 blocks.
// ============================================================================
__global__ __launch_bounds__(128) void k_gemm1(const float* __restrict__ X) {
    __shared__ __align__(16) float xs[32][132];    // [w][h]
    __shared__ __align__(16) float fxd[32][132];   // [w][2m] duplicated

    const int ht = blockIdx.x >> 1, ws = blockIdx.x & 1;
    const int b = blockIdx.z, c = blockIdx.y;
    const int h0 = ht * 128, w0 = ws * 256;
    const float* Xbc = X + (((size_t)b * CC + c) * HH + h0) * WW + w0;
    const float* Fxb = g_Fx + (size_t)b * 64 * 512 + w0;

    const int tid = threadIdx.x;
    const int tm = tid & 7;      // m = tm*8 + j
    const int th = tid >> 3;     // h = th*8 + {0..7}
    const int lw = (tid & 7) * 4;
    const int lr = tid >> 3;     // 0..15

    ull acc2[4][8];              // [h-pair][m]
#pragma unroll
    for (int i = 0; i < 4; i++)
#pragma unroll
        for (int j = 0; j < 8; j++) acc2[i][j] = 0ull;

    for (int wc = 0; wc < 256; wc += 32) {
        // X tile: 128h x 32w -> xs[w][h]
#pragma unroll
        for (int it = 0; it < 8; it++) {
            const int h = lr + it * 16;
            const float4 v = *(const float4*)&Xbc[h * 512 + wc + lw];
            xs[lw + 0][h] = v.x; xs[lw + 1][h] = v.y;
            xs[lw + 2][h] = v.z; xs[lw + 3][h] = v.w;
        }
        // Fx tile: 64m x 32w -> fxd[w][2m] duplicated
#pragma unroll
        for (int it = 0; it < 4; it++) {
            const int mm = lr + it * 16;
            const float4 v = *(const float4*)&Fxb[mm * 512 + wc + lw];
            *(float2*)&fxd[lw + 0][2 * mm] = make_float2(v.x, v.x);
            *(float2*)&fxd[lw + 1][2 * mm] = make_float2(v.y, v.y);
            *(float2*)&fxd[lw + 2][2 * mm] = make_float2(v.z, v.z);
            *(float2*)&fxd[lw + 3][2 * mm] = make_float2(v.w, v.w);
        }
        __syncthreads();

#pragma unroll 4
        for (int w = 0; w < 32; w++) {
            const ulonglong2 xa = *(const ulonglong2*)&xs[w][th * 8];
            const ulonglong2 xb = *(const ulonglong2*)&xs[w][th * 8 + 4];
            ull xv[4] = {xa.x, xa.y, xb.x, xb.y};
            ull fv[8];
#pragma unroll
            for (int jj = 0; jj < 4; jj++) {
                const ulonglong2 f = *(const ulonglong2*)&fxd[w][tm * 16 + 4 * jj];
                fv[2 * jj] = f.x; fv[2 * jj + 1] = f.y;
            }
#pragma unroll
            for (int i = 0; i < 4; i++)
#pragma unroll
                for (int j = 0; j < 8; j++)
                    acc2[i][j] = fma2(xv[i], fv[j], acc2[i][j]);
        }
        __syncthreads();
    }

    float* G = g_GxP[ws] + (((size_t)b * CC + c) * HH + h0) * 64;
#pragma unroll
    for (int i = 0; i < 4; i++) {
        float2 a[8];
#pragma unroll
        for (int j = 0; j < 8; j++) a[j] = unpack2(acc2[i][j]);
        const int he = th * 8 + 2 * i;
        *(float4*)&G[(he + 0) * 64 + tm * 8 + 0] = make_float4(a[0].x, a[1].x, a[2].x, a[3].x);
        *(float4*)&G[(he + 0) * 64 + tm * 8 + 4] = make_float4(a[4].x, a[5].x, a[6].x, a[7].x);
        *(float4*)&G[(he + 1) * 64 + tm * 8 + 0] = make_float4(a[0].y, a[1].y, a[2].y, a[3].y);
        *(float4*)&G[(he + 1) * 64 + tm * 8 + 4] = make_float4(a[4].y, a[5].y, a[6].y, a[7].y);
    }
}

// ============================================================================
// K4: out[b,c,n,m] = sum_h Fy'[b,n,h] * (GxA + GxB)[b,c,h,m]
// One block per (c,b): 64n x 64m, 256 threads, thread 2n x 8m (m-pairs).
// ============================================================================
__global__ __launch_bounds__(256) void k_gemm2(float* __restrict__ out) {
    __shared__ __align__(16) float gxs[32][68];    // [h][m]
    __shared__ __align__(16) float fyd[32][132];   // [h][2n] duplicated

    const int c = blockIdx.x, b = blockIdx.y;
    const size_t gidx = ((size_t)b * CC + c) * HH * 64;
    const float* GA = g_GxP[0] + gidx;
    const float* GB = g_GxP[1] + gidx;
    const float* Fyb = g_Fy + (size_t)b * 64 * 512;

    const int tid = threadIdx.x;
    const int tm = tid & 7;      // m = tm*8 + 2q(+0/1)
    const int tn = tid >> 3;     // n = tn*2 + i

    ull acc2[2][4];
#pragma unroll
    for (int i = 0; i < 2; i++)
#pragma unroll
        for (int q = 0; q < 4; q++) acc2[i][q] = 0ull;

    for (int hc = 0; hc < 512; hc += 32) {
        // Gx tile: 32h x 64m, sum of the two w-split partials
        {
#pragma unroll
            for (int s = 0; s < 2; s++) {
                const int f4 = tid * 2 + s;       // 0..511
                const int h = f4 >> 4;            // 0..31
                const int m4 = (f4 & 15) * 4;
                const float4 va = *(const float4*)&GA[(hc + h) * 64 + m4];
                const float4 vb = *(const float4*)&GB[(hc + h) * 64 + m4];
                *(float4*)&gxs[h][m4] =
                    make_float4(va.x + vb.x, va.y + vb.y, va.z + vb.z, va.w + vb.w);
            }
        }
        // Fy tile: 64n x 32h -> fyd[h][2n] duplicated
        {
            const int n = tid >> 2;               // 0..63
            const int h0 = (tid & 3) * 8;
            const float4 v0 = *(const float4*)&Fyb[n * 512 + hc + h0];
            const float4 v1 = *(const float4*)&Fyb[n * 512 + hc + h0 + 4];
            *(float2*)&fyd[h0 + 0][2 * n] = make_float2(v0.x, v0.x);
            *(float2*)&fyd[h0 + 1][2 * n] = make_float2(v0.y, v0.y);
            *(float2*)&fyd[h0 + 2][2 * n] = make_float2(v0.z, v0.z);
            *(float2*)&fyd[h0 + 3][2 * n] = make_float2(v0.w, v0.w);
            *(float2*)&fyd[h0 + 4][2 * n] = make_float2(v1.x, v1.x);
            *(float2*)&fyd[h0 + 5][2 * n] = make_float2(v1.y, v1.y);
            *(float2*)&fyd[h0 + 6][2 * n] = make_float2(v1.z, v1.z);
            *(float2*)&fyd[h0 + 7][2 * n] = make_float2(v1.w, v1.w);
        }
        __syncthreads();

#pragma unroll 4
        for (int h = 0; h < 32; h++) {
            const ulonglong2 f = *(const ulonglong2*)&fyd[h][tn * 4];
            const ulonglong2 g0 = *(const ulonglong2*)&gxs[h][tm * 8];
            const ulonglong2 g1 = *(const ulonglong2*)&gxs[h][tm * 8 + 4];
            acc2[0][0] = fma2(f.x, g0.x, acc2[0][0]);
            acc2[0][1] = fma2(f.x, g0.y, acc2[0][1]);
            acc2[0][2] = fma2(f.x, g1.x, acc2[0][2]);
            acc2[0][3] = fma2(f.x, g1.y, acc2[0][3]);
            acc2[1][0] = fma2(f.y, g0.x, acc2[1][0]);
            acc2[1][1] = fma2(f.y, g0.y, acc2[1][1]);
            acc2[1][2] = fma2(f.y, g1.x, acc2[1][2]);
            acc2[1][3] = fma2(f.y, g1.y, acc2[1][3]);
        }
        __syncthreads();
    }

    float* O = out + ((size_t)b * CC + c) * 64 * 64;
#pragma unroll
    for (int i = 0; i < 2; i++) {
        const int n = tn * 2 + i;
        const float2 a0 = unpack2(acc2[i][0]);
        const float2 a1 = unpack2(acc2[i][1]);
        const float2 a2 = unpack2(acc2[i][2]);
        const float2 a3 = unpack2(acc2[i][3]);
        *(float4*)&O[n * 64 + tm * 8 + 0] = make_float4(a0.x, a0.y, a1.x, a1.y);
        *(float4*)&O[n * 64 + tm * 8 + 4] = make_float4(a2.x, a2.y, a3.x, a3.y);
    }
}

// ============================================================================
extern "C" void kernel_launch(void* const* d_in, const int* in_sizes, int n_in,
                              void* d_out, int out_size) {
    (void)in_sizes; (void)n_in; (void)out_size;
    const float* X    = (const float*)d_in[0];
    const float* Wl   = (const float*)d_in[1];
    const float* bloc = (const float*)d_in[2];
    float* out = (float*)d_out;

    k_locnet<<<NBLK1, 256>>>(X, Wl);
    k_reduce_p<<<160, 32>>>(bloc);
    k_filters<<<dim3(64, 2, 32), 128>>>();
    k_gemm1<<<dim3(8, 3, 32), 128>>>(X);
    k_gemm2<<<dim3(3, 32), 256>>>(out);
}

// round 4
// speedup vs baseline: 2.0619x; 2.0619x over previous
#include <cuda_runtime.h>
#include <cstdint>

typedef unsigned long long ull;

// ---------------- problem constants ----------------
#define BB 32
#define CC 3
#define HH 512
#define WW 512
#define NX 64
#define NY 64
#define KTOT (CC*HH*WW)          // 786432
#define NBLK1 384                // locnet blocks: 384 * 2048 = 786432

// ---------------- device scratch ----------------
__device__ float g_partial[160 * NBLK1];      // t-major: [t][g]
__device__ float g_p[BB * 5];
__device__ float g_Fx[BB * NX * WW];          // [b][nx][w]
__device__ float g_Fy[BB * NY * HH];          // [b][ny][h], * gamma
__device__ float g_GxP[2][BB * CC * HH * NX]; // w-split partials

// ---------------- packed f32x2 helpers ----------------
__device__ __forceinline__ ull pack2(float lo, float hi) {
    ull r;
    asm("mov.b64 %0, {%1, %2};" : "=l"(r) : "f"(lo), "f"(hi));
    return r;
}
__device__ __forceinline__ ull fma2(ull a, ull b, ull c) {
    ull d;
    asm("fma.rn.f32x2 %0, %1, %2, %3;" : "=l"(d) : "l"(a), "l"(b), "l"(c));
    return d;
}
__device__ __forceinline__ float2 unpack2(ull v) {
    float2 f;
    asm("mov.b64 {%0, %1}, %2;" : "=f"(f.x), "=f"(f.y) : "l"(v));
    return f;
}

// ============================================================================
// K1: locnet. Block covers 2048 k. W chunk transposed into smem (read once,
// conflict-free LDS.128). Each warp owns 4 batches -> per-(b,j) reduction has
// a unique warp owner: NO atomics. 100 SHFL per thread total.
// ============================================================================
__global__ __launch_bounds__(256) void k_locnet(const float* __restrict__ X,
                                                const float* __restrict__ Wl) {
    __shared__ __align__(16) float Wt[5][2052];
    __shared__ float ps[160];

    const int tid = threadIdx.x;
    const int base = blockIdx.x * 2048;

    // Load W chunk (10240 contiguous floats) coalesced, scatter-transpose.
    {
        const float* src = Wl + (size_t)base * 5;
#pragma unroll
        for (int it = 0; it < 10; it++) {
            const int e4 = tid * 4 + it * 1024;
            const float4 v = *(const float4*)&src[e4];
            const float vv[4] = {v.x, v.y, v.z, v.w};
#pragma unroll
            for (int r = 0; r < 4; r++) {
                const int e = e4 + r;
                Wt[e % 5][e / 5] = vv[r];
            }
        }
    }
    __syncthreads();

    const int lane = tid & 31;
    const int warp = tid >> 5;
    const int b0 = warp * 4;

    float acc[4][5];
#pragma unroll
    for (int bb = 0; bb < 4; bb++)
#pragma unroll
        for (int j = 0; j < 5; j++) acc[bb][j] = 0.0f;

#pragma unroll 4
    for (int qi = 0; qi < 16; qi++) {
        const int k = qi * 128 + lane * 4;
        float4 wv[5];
#pragma unroll
        for (int j = 0; j < 5; j++) wv[j] = *(const float4*)&Wt[j][k];
#pragma unroll
        for (int bb = 0; bb < 4; bb++) {
            const float4 x = *(const float4*)&X[(size_t)(b0 + bb) * KTOT + base + k];
#pragma unroll
            for (int j = 0; j < 5; j++) {
                acc[bb][j] = fmaf(x.x, wv[j].x, acc[bb][j]);
                acc[bb][j] = fmaf(x.y, wv[j].y, acc[bb][j]);
                acc[bb][j] = fmaf(x.z, wv[j].z, acc[bb][j]);
                acc[bb][j] = fmaf(x.w, wv[j].w, acc[bb][j]);
            }
        }
    }

#pragma unroll
    for (int bb = 0; bb < 4; bb++)
#pragma unroll
        for (int j = 0; j < 5; j++) {
            float v = acc[bb][j];
#pragma unroll
            for (int off = 16; off > 0; off >>= 1)
                v += __shfl_down_sync(0xffffffffu, v, off);
            if (lane == 0) ps[(b0 + bb) * 5 + j] = v;
        }
    __syncthreads();
    if (tid < 160) g_partial[tid * NBLK1 + blockIdx.x] = ps[tid];
}

// K1b: final reduce + bias. One 32-lane block per output t (coalesced).
__global__ __launch_bounds__(32) void k_reduce_p(const float* __restrict__ b_loc) {
    const int t = blockIdx.x;
    const int lane = threadIdx.x;
    const float* src = g_partial + (size_t)t * NBLK1;
    float s = 0.0f;
#pragma unroll
    for (int i = 0; i < NBLK1 / 32; i++) s += src[lane + i * 32];
#pragma unroll
    for (int off = 16; off > 0; off >>= 1)
        s += __shfl_down_sync(0xffffffffu, s, off);
    if (lane == 0) g_p[t] = s + b_loc[t % 5];
}

// ============================================================================
// K2: filter banks. grid (64, 2, 32). gamma folded into Fy.
// ============================================================================
__global__ __launch_bounds__(128) void k_filters() {
    const int n = blockIdx.x;
    const int axis = blockIdx.y;
    const int b = blockIdx.z;
    const int tid = threadIdx.x;

    const float* pb = g_p + b * 5;
    const float sigma2 = expf(pb[2]);
    const float delta = expf(pb[3]) * (511.0f / 63.0f);
    const float gctr = (axis == 0) ? 32.0f * (pb[0] + 1.0f) : 32.0f * (pb[1] + 1.0f);
    const float m = gctr + delta * ((float)n - 32.5f);
    const float inv2s = 1.0f / (2.0f * sigma2);

    float vals[4];
    float lsum = 0.0f;
#pragma unroll
    for (int i = 0; i < 4; i++) {
        const float a = (float)(tid + i * 128);
        const float d = a - m;
        const float e = expf(-d * d * inv2s);
        vals[i] = e;
        lsum += e;
    }
    __shared__ float sw[4];
#pragma unroll
    for (int off = 16; off > 0; off >>= 1)
        lsum += __shfl_down_sync(0xffffffffu, lsum, off);
    if ((tid & 31) == 0) sw[tid >> 5] = lsum;
    __syncthreads();
    const float tot = sw[0] + sw[1] + sw[2] + sw[3];
    float scale = 1.0f / (tot + 1e-4f);
    if (axis == 1) scale *= expf(pb[4]);

    float* dst = (axis == 0 ? g_Fx : g_Fy) + ((size_t)b * 64 + n) * 512;
#pragma unroll
    for (int i = 0; i < 4; i++) dst[tid + i * 128] = vals[i] * scale;
}

// ============================================================================
// K3: GxP[ws] = partial sum over 256 w. Block 128h x 64m, 128 threads,
// thread tile 8h x 8m. Accumulate in f32x2 over m-pairs: f via natural
// LDS.64 (m = tm*2 + q*16 interleave, conflict-free), x via pack2 broadcast
// (R1-proven). grid (4 ht * 2 ws, 3, 32) = 768 blocks.
// ============================================================================
__global__ __launch_bounds__(128) void k_gemm1(const float* __restrict__ X) {
    __shared__ __align__(16) float xs[32][129];   // [w][h] (129: conflict-free)
    __shared__ __align__(16) float fxs[32][66];   // [w][m]

    const int ht = blockIdx.x >> 1, ws = blockIdx.x & 1;
    const int b = blockIdx.z, c = blockIdx.y;
    const int h0 = ht * 128, w0 = ws * 256;
    const float* Xbc = X + (((size_t)b * CC + c) * HH + h0) * WW + w0;
    const float* Fxb = g_Fx + (size_t)b * 64 * 512 + w0;

    const int tid = threadIdx.x;
    const int tm = tid & 7;      // m = tm*2 + q*16 (+0/1)
    const int th = tid >> 3;     // h = th*8 + i
    const int lw = (tid & 7) * 4;
    const int lr = tid >> 3;     // 0..15

    ull acc2[8][4];              // [h][m-pair]
#pragma unroll
    for (int i = 0; i < 8; i++)
#pragma unroll
        for (int q = 0; q < 4; q++) acc2[i][q] = 0ull;

    for (int wc = 0; wc < 256; wc += 32) {
        // X tile: 128h x 32w -> xs[w][h]
#pragma unroll
        for (int it = 0; it < 8; it++) {
            const int h = lr + it * 16;
            const float4 v = *(const float4*)&Xbc[h * 512 + wc + lw];
            xs[lw + 0][h] = v.x; xs[lw + 1][h] = v.y;
            xs[lw + 2][h] = v.z; xs[lw + 3][h] = v.w;
        }
        // Fx tile: 64m x 32w -> fxs[w][m]
#pragma unroll
        for (int it = 0; it < 4; it++) {
            const int mm = lr + it * 16;
            const float4 v = *(const float4*)&Fxb[mm * 512 + wc + lw];
            fxs[lw + 0][mm] = v.x; fxs[lw + 1][mm] = v.y;
            fxs[lw + 2][mm] = v.z; fxs[lw + 3][mm] = v.w;
        }
        __syncthreads();

#pragma unroll 8
        for (int w = 0; w < 32; w++) {
            ull fv[4];
#pragma unroll
            for (int q = 0; q < 4; q++)
                fv[q] = *(const ull*)&fxs[w][tm * 2 + q * 16];
            ull xv[8];
#pragma unroll
            for (int i = 0; i < 8; i++) {
                const float x = xs[w][th * 8 + i];
                xv[i] = pack2(x, x);
            }
#pragma unroll
            for (int i = 0; i < 8; i++)
#pragma unroll
                for (int q = 0; q < 4; q++)
                    acc2[i][q] = fma2(xv[i], fv[q], acc2[i][q]);
        }
        __syncthreads();
    }

    float* G = g_GxP[ws] + (((size_t)b * CC + c) * HH + h0) * 64;
#pragma unroll
    for (int i = 0; i < 8; i++) {
        const int h = th * 8 + i;
#pragma unroll
        for (int q = 0; q < 4; q++) {
            const float2 a = unpack2(acc2[i][q]);
            *(float2*)&G[h * 64 + tm * 2 + q * 16] = a;
        }
    }
}

// ============================================================================
// K4: out[b,c,n,m] = sum_h Fy'[b,n,h] * (GxA + GxB)[b,c,h,m]
// One block per (c,b): 64n x 64m, 256 threads, thread 2n x 8m (m-pairs).
// ============================================================================
__global__ __launch_bounds__(256) void k_gemm2(float* __restrict__ out) {
    __shared__ __align__(16) float gxs[32][68];    // [h][m]
    __shared__ __align__(16) float fyd[32][132];   // [h][2n] duplicated

    const int c = blockIdx.x, b = blockIdx.y;
    const size_t gidx = ((size_t)b * CC + c) * HH * 64;
    const float* GA = g_GxP[0] + gidx;
    const float* GB = g_GxP[1] + gidx;
    const float* Fyb = g_Fy + (size_t)b * 64 * 512;

    const int tid = threadIdx.x;
    const int tm = tid & 7;      // m = tm*8 + 2q(+0/1)
    const int tn = tid >> 3;     // n = tn*2 + i

    ull acc2[2][4];
#pragma unroll
    for (int i = 0; i < 2; i++)
#pragma unroll
        for (int q = 0; q < 4; q++) acc2[i][q] = 0ull;

    for (int hc = 0; hc < 512; hc += 32) {
        // Gx tile: 32h x 64m, summing the two w-split partials
        {
#pragma unroll
            for (int s = 0; s < 2; s++) {
                const int f4 = tid * 2 + s;
                const int h = f4 >> 4;
                const int m4 = (f4 & 15) * 4;
                const float4 va = *(const float4*)&GA[(hc + h) * 64 + m4];
                const float4 vb = *(const float4*)&GB[(hc + h) * 64 + m4];
                *(float4*)&gxs[h][m4] =
                    make_float4(va.x + vb.x, va.y + vb.y, va.z + vb.z, va.w + vb.w);
            }
        }
        // Fy tile: 64n x 32h -> fyd[h][2n] duplicated
        {
            const int n = tid >> 2;
            const int h0 = (tid & 3) * 8;
            const float4 v0 = *(const float4*)&Fyb[n * 512 + hc + h0];
            const float4 v1 = *(const float4*)&Fyb[n * 512 + hc + h0 + 4];
            *(float2*)&fyd[h0 + 0][2 * n] = make_float2(v0.x, v0.x);
            *(float2*)&fyd[h0 + 1][2 * n] = make_float2(v0.y, v0.y);
            *(float2*)&fyd[h0 + 2][2 * n] = make_float2(v0.z, v0.z);
            *(float2*)&fyd[h0 + 3][2 * n] = make_float2(v0.w, v0.w);
            *(float2*)&fyd[h0 + 4][2 * n] = make_float2(v1.x, v1.x);
            *(float2*)&fyd[h0 + 5][2 * n] = make_float2(v1.y, v1.y);
            *(float2*)&fyd[h0 + 6][2 * n] = make_float2(v1.z, v1.z);
            *(float2*)&fyd[h0 + 7][2 * n] = make_float2(v1.w, v1.w);
        }
        __syncthreads();

#pragma unroll 4
        for (int h = 0; h < 32; h++) {
            const ulonglong2 f = *(const ulonglong2*)&fyd[h][tn * 4];
            const ulonglong2 g0 = *(const ulonglong2*)&gxs[h][tm * 8];
            const ulonglong2 g1 = *(const ulonglong2*)&gxs[h][tm * 8 + 4];
            acc2[0][0] = fma2(f.x, g0.x, acc2[0][0]);
            acc2[0][1] = fma2(f.x, g0.y, acc2[0][1]);
            acc2[0][2] = fma2(f.x, g1.x, acc2[0][2]);
            acc2[0][3] = fma2(f.x, g1.y, acc2[0][3]);
            acc2[1][0] = fma2(f.y, g0.x, acc2[1][0]);
            acc2[1][1] = fma2(f.y, g0.y, acc2[1][1]);
            acc2[1][2] = fma2(f.y, g1.x, acc2[1][2]);
            acc2[1][3] = fma2(f.y, g1.y, acc2[1][3]);
        }
        __syncthreads();
    }

    float* O = out + ((size_t)b * CC + c) * 64 * 64;
#pragma unroll
    for (int i = 0; i < 2; i++) {
        const int n = tn * 2 + i;
        const float2 a0 = unpack2(acc2[i][0]);
        const float2 a1 = unpack2(acc2[i][1]);
        const float2 a2 = unpack2(acc2[i][2]);
        const float2 a3 = unpack2(acc2[i][3]);
        *(float4*)&O[n * 64 + tm * 8 + 0] = make_float4(a0.x, a0.y, a1.x, a1.y);
        *(float4*)&O[n * 64 + tm * 8 + 4] = make_float4(a2.x, a2.y, a3.x, a3.y);
    }
}

// ============================================================================
extern "C" void kernel_launch(void* const* d_in, const int* in_sizes, int n_in,
                              void* d_out, int out_size) {
    (void)in_sizes; (void)n_in; (void)out_size;
    const float* X    = (const float*)d_in[0];
    const float* Wl   = (const float*)d_in[1];
    const float* bloc = (const float*)d_in[2];
    float* out = (float*)d_out;

    k_locnet<<<NBLK1, 256>>>(X, Wl);
    k_reduce_p<<<160, 32>>>(bloc);
    k_filters<<<dim3(64, 2, 32), 128>>>();
    k_gemm1<<<dim3(8, 3, 32), 128>>>(X);
    k_gemm2<<<dim3(3, 32), 256>>>(out);
}

// round 6
// speedup vs baseline: 2.5319x; 1.2279x over previous
#include <cuda_runtime.h>
#include <cuda_bf16.h>
#include <cstdint>

typedef unsigned long long ull;

// ---------------- problem constants ----------------
#define BB 32
#define CC 3
#define HH 512
#define WW 512
#define KTOT (CC*HH*WW)
#define NBLK1 384

// ---------------- device scratch ----------------
__device__ float g_partial[160 * NBLK1];
__device__ float g_p[BB * 5];
__device__ float g_Fx[BB * 64 * WW];
__device__ float g_Fy[BB * 64 * HH];
__device__ float g_Gx[BB * CC * HH * 64];
__device__ float g_outP[4][96 * 4096];

// ---------------- f32x2 helpers ----------------
__device__ __forceinline__ ull fma2(ull a, ull b, ull c) {
    ull d;
    asm("fma.rn.f32x2 %0, %1, %2, %3;" : "=l"(d) : "l"(a), "l"(b), "l"(c));
    return d;
}
__device__ __forceinline__ float2 unpack2(ull v) {
    float2 f;
    asm("mov.b64 {%0, %1}, %2;" : "=f"(f.x), "=f"(f.y) : "l"(v));
    return f;
}
__device__ __forceinline__ uint32_t smem_u32(const void* p) {
    uint32_t a;
    asm("{ .reg .u64 t; cvta.to.shared.u64 t, %1; cvt.u32.u64 %0, t; }" : "=r"(a) : "l"(p));
    return a;
}
#define SWZ(o) ((o) ^ (((o) >> 3) & 0x70))

__device__ __forceinline__ void ldsm_x4(uint32_t addr, uint32_t& r0, uint32_t& r1,
                                        uint32_t& r2, uint32_t& r3) {
    asm volatile("ldmatrix.sync.aligned.m8n8.x4.shared.b16 {%0,%1,%2,%3}, [%4];"
                 : "=r"(r0), "=r"(r1), "=r"(r2), "=r"(r3) : "r"(addr));
}
__device__ __forceinline__ void mma_bf16(float* c, const uint32_t* a, const uint32_t* b) {
    asm volatile(
        "mma.sync.aligned.m16n8k16.row.col.f32.bf16.bf16.f32 "
        "{%0,%1,%2,%3}, {%4,%5,%6,%7}, {%8,%9}, {%0,%1,%2,%3};"
        : "+f"(c[0]), "+f"(c[1]), "+f"(c[2]), "+f"(c[3])
        : "r"(a[0]), "r"(a[1]), "r"(a[2]), "r"(a[3]), "r"(b[0]), "r"(b[1]));
}

// split a float4 into packed bf16x2 hi and lo words
__device__ __forceinline__ void split4(float4 v, uint2& hv, uint2& lv) {
    __nv_bfloat16 h0 = __float2bfloat16_rn(v.x);
    __nv_bfloat16 h1 = __float2bfloat16_rn(v.y);
    __nv_bfloat16 h2 = __float2bfloat16_rn(v.z);
    __nv_bfloat16 h3 = __float2bfloat16_rn(v.w);
    __nv_bfloat16 l0 = __float2bfloat16_rn(v.x - __bfloat162float(h0));
    __nv_bfloat16 l1 = __float2bfloat16_rn(v.y - __bfloat162float(h1));
    __nv_bfloat16 l2 = __float2bfloat16_rn(v.z - __bfloat162float(h2));
    __nv_bfloat16 l3 = __float2bfloat16_rn(v.w - __bfloat162float(h3));
    hv.x = (uint32_t)__bfloat16_as_ushort(h0) | ((uint32_t)__bfloat16_as_ushort(h1) << 16);
    hv.y = (uint32_t)__bfloat16_as_ushort(h2) | ((uint32_t)__bfloat16_as_ushort(h3) << 16);
    lv.x = (uint32_t)__bfloat16_as_ushort(l0) | ((uint32_t)__bfloat16_as_ushort(l1) << 16);
    lv.y = (uint32_t)__bfloat16_as_ushort(l2) | ((uint32_t)__bfloat16_as_ushort(l3) << 16);
}

// ============================================================================
// K1: locnet (R4-proven)
// ============================================================================
__global__ __launch_bounds__(256) void k_locnet(const float* __restrict__ X,
                                                const float* __restrict__ Wl) {
    __shared__ __align__(16) float Wt[5][2052];
    __shared__ float ps[160];
    const int tid = threadIdx.x;
    const int base = blockIdx.x * 2048;
    {
        const float* src = Wl + (size_t)base * 5;
#pragma unroll
        for (int it = 0; it < 10; it++) {
            const int e4 = tid * 4 + it * 1024;
            const float4 v = *(const float4*)&src[e4];
            const float vv[4] = {v.x, v.y, v.z, v.w};
#pragma unroll
            for (int r = 0; r < 4; r++) {
                const int e = e4 + r;
                Wt[e % 5][e / 5] = vv[r];
            }
        }
    }
    __syncthreads();
    const int lane = tid & 31, warp = tid >> 5;
    const int b0 = warp * 4;
    float acc[4][5];
#pragma unroll
    for (int bb = 0; bb < 4; bb++)
#pragma unroll
        for (int j = 0; j < 5; j++) acc[bb][j] = 0.0f;
#pragma unroll 4
    for (int qi = 0; qi < 16; qi++) {
        const int k = qi * 128 + lane * 4;
        float4 wv[5];
#pragma unroll
        for (int j = 0; j < 5; j++) wv[j] = *(const float4*)&Wt[j][k];
#pragma unroll
        for (int bb = 0; bb < 4; bb++) {
            const float4 x = *(const float4*)&X[(size_t)(b0 + bb) * KTOT + base + k];
#pragma unroll
            for (int j = 0; j < 5; j++) {
                acc[bb][j] = fmaf(x.x, wv[j].x, acc[bb][j]);
                acc[bb][j] = fmaf(x.y, wv[j].y, acc[bb][j]);
                acc[bb][j] = fmaf(x.z, wv[j].z, acc[bb][j]);
                acc[bb][j] = fmaf(x.w, wv[j].w, acc[bb][j]);
            }
        }
    }
#pragma unroll
    for (int bb = 0; bb < 4; bb++)
#pragma unroll
        for (int j = 0; j < 5; j++) {
            float v = acc[bb][j];
#pragma unroll
            for (int off = 16; off > 0; off >>= 1)
                v += __shfl_down_sync(0xffffffffu, v, off);
            if (lane == 0) ps[(b0 + bb) * 5 + j] = v;
        }
    __syncthreads();
    if (tid < 160) g_partial[tid * NBLK1 + blockIdx.x] = ps[tid];
}

__global__ __launch_bounds__(32) void k_reduce_p(const float* __restrict__ b_loc) {
    const int t = blockIdx.x, lane = threadIdx.x;
    const float* src = g_partial + (size_t)t * NBLK1;
    float s = 0.0f;
#pragma unroll
    for (int i = 0; i < NBLK1 / 32; i++) s += src[lane + i * 32];
#pragma unroll
    for (int off = 16; off > 0; off >>= 1)
        s += __shfl_down_sync(0xffffffffu, s, off);
    if (lane == 0) g_p[t] = s + b_loc[t % 5];
}

// ============================================================================
// K2: filter banks (unchanged)
// ============================================================================
__global__ __launch_bounds__(128) void k_filters() {
    const int n = blockIdx.x, axis = blockIdx.y, b = blockIdx.z;
    const int tid = threadIdx.x;
    const float* pb = g_p + b * 5;
    const float sigma2 = expf(pb[2]);
    const float delta = expf(pb[3]) * (511.0f / 63.0f);
    const float gctr = (axis == 0) ? 32.0f * (pb[0] + 1.0f) : 32.0f * (pb[1] + 1.0f);
    const float m = gctr + delta * ((float)n - 32.5f);
    const float inv2s = 1.0f / (2.0f * sigma2);
    float vals[4], lsum = 0.0f;
#pragma unroll
    for (int i = 0; i < 4; i++) {
        const float a = (float)(tid + i * 128);
        const float d = a - m;
        const float e = expf(-d * d * inv2s);
        vals[i] = e; lsum += e;
    }
    __shared__ float sw[4];
#pragma unroll
    for (int off = 16; off > 0; off >>= 1)
        lsum += __shfl_down_sync(0xffffffffu, lsum, off);
    if ((tid & 31) == 0) sw[tid >> 5] = lsum;
    __syncthreads();
    const float tot = sw[0] + sw[1] + sw[2] + sw[3];
    float scale = 1.0f / (tot + 1e-4f);
    if (axis == 1) scale *= expf(pb[4]);
    float* dst = (axis == 0 ? g_Fx : g_Fy) + ((size_t)b * 64 + n) * 512;
#pragma unroll
    for (int i = 0; i < 4; i++) dst[tid + i * 128] = vals[i] * scale;
}

// ============================================================================
// K3: GEMM1 via mma.sync bf16 hi/lo (3-term compensated).
// Gx[h,m] = sum_w X[h,w]*Fx[m,w].  CTA: 128h x 64m, K=512 in 8 chunks of 64.
// 8 warps, each 16h x 64m. A row-major, B col-major (both K-contiguous).
// smem per buffer: XH 16K | XL 16K | FH 8K | FL 8K = 48K, double-buffered.
// grid (4 ht, 3 c, 32 b) = 384 CTAs, 256 threads.
// ============================================================================
#define PBUF 49152
#define GEMM1_DYN (2 * PBUF)

__global__ __launch_bounds__(256) void k_gemm1_mma(const float* __restrict__ X) {
    extern __shared__ __align__(1024) char smem[];
    const uint32_t sbase = smem_u32(smem);

    const int tid = threadIdx.x;
    const int wid = tid >> 5, lane = tid & 31;
    const int ht = blockIdx.x, c = blockIdx.y, b = blockIdx.z;
    const int h0 = ht * 128;
    const float* Xbc = X + (((size_t)b * CC + c) * HH + h0) * WW;
    const float* Fxb = g_Fx + (size_t)b * 64 * 512;

    float acc[8][4];
#pragma unroll
    for (int nt = 0; nt < 8; nt++)
#pragma unroll
        for (int r = 0; r < 4; r++) acc[nt][r] = 0.0f;

    // ldmatrix source addresses (within-plane byte offsets, pre-swizzled parts
    // computed per use). A: row = wid*16 + (lane&15), k-half = (lane>>4)*8.
    const int aRow = wid * 16 + (lane & 15);
    const int aK8 = (lane >> 4) * 8;
    // B: n = ((lane>>4)<<3) + (lane&7) (+nb), k-half = ((lane>>3)&1)*8
    const int bN = ((lane >> 4) << 3) + (lane & 7);
    const int bK8 = ((lane >> 3) & 1) * 8;

    for (int ch = 0; ch < 8; ch++) {
        const uint32_t bufU = sbase + (ch & 1) * PBUF;
        char* bufP = smem + (ch & 1) * PBUF;
        const int w0 = ch * 64;

        // ---- load + split X chunk: 128h x 64w ----
        {
            const int r0 = tid >> 4;            // 0..15
            const int c4 = (tid & 15) * 4;      // 0..60
#pragma unroll
            for (int p = 0; p < 8; p++) {
                const int row = r0 + p * 16;
                const float4 v = *(const float4*)&Xbc[row * 512 + w0 + c4];
                uint2 hv, lv;
                split4(v, hv, lv);
                const uint32_t so = SWZ((uint32_t)(row * 128 + c4 * 2));
                *(uint2*)(bufP + so) = hv;              // XH plane at 0
                *(uint2*)(bufP + 16384 + so) = lv;      // XL plane
            }
        }
        // ---- load + split Fx chunk: 64m x 64w ----
        {
            const int m = tid >> 2;             // 0..63
            const int cb = (tid & 3) * 16;
#pragma unroll
            for (int q = 0; q < 4; q++) {
                const int c4 = cb + q * 4;
                const float4 v = *(const float4*)&Fxb[m * 512 + w0 + c4];
                uint2 hv, lv;
                split4(v, hv, lv);
                const uint32_t so = SWZ((uint32_t)(m * 128 + c4 * 2));
                *(uint2*)(bufP + 32768 + so) = hv;      // FH plane
                *(uint2*)(bufP + 40960 + so) = lv;      // FL plane
            }
        }
        __syncthreads();

        const uint32_t XH = bufU, XL = bufU + 16384;
        const uint32_t FH = bufU + 32768, FL = bufU + 40960;

#pragma unroll
        for (int kc = 0; kc < 64; kc += 16) {
            uint32_t ah[4], al[4];
            {
                const uint32_t off = SWZ((uint32_t)(aRow * 128 + (kc + aK8) * 2));
                ldsm_x4(XH + off, ah[0], ah[1], ah[2], ah[3]);
                ldsm_x4(XL + off, al[0], al[1], al[2], al[3]);
            }
            uint32_t bh[16], bl[16];
#pragma unroll
            for (int nb = 0; nb < 4; nb++) {
                const uint32_t off =
                    SWZ((uint32_t)((bN + nb * 16) * 128 + (kc + bK8) * 2));
                ldsm_x4(FH + off, bh[nb * 4 + 0], bh[nb * 4 + 1],
                        bh[nb * 4 + 2], bh[nb * 4 + 3]);
                ldsm_x4(FL + off, bl[nb * 4 + 0], bl[nb * 4 + 1],
                        bl[nb * 4 + 2], bl[nb * 4 + 3]);
            }
#pragma unroll
            for (int nt = 0; nt < 8; nt++) {
                mma_bf16(acc[nt], ah, &bh[nt * 2]);   // hi * hi
                mma_bf16(acc[nt], ah, &bl[nt * 2]);   // hi * lo
                mma_bf16(acc[nt], al, &bh[nt * 2]);   // lo * hi
            }
        }
        __syncthreads();
    }

    // epilogue: acc[nt] rows (lane>>2, +8), cols nt*8 + (lane&3)*2
    float* G = g_Gx + (((size_t)b * CC + c) * HH + h0) * 64;
    const int r0 = wid * 16 + (lane >> 2);
    const int c0 = (lane & 3) * 2;
#pragma unroll
    for (int nt = 0; nt < 8; nt++) {
        *(float2*)&G[(r0 + 0) * 64 + nt * 8 + c0] = make_float2(acc[nt][0], acc[nt][1]);
        *(float2*)&G[(r0 + 8) * 64 + nt * 8 + c0] = make_float2(acc[nt][2], acc[nt][3]);
    }
}

// ============================================================================
// K4: partial out over h-range of 128. grid (4 ht, 3 c, 32 b), 256 thr.
// ============================================================================
__global__ __launch_bounds__(256) void k_gemm2() {
    __shared__ __align__(16) float gxs[32][68];
    __shared__ __align__(16) float fyd[32][132];

    const int ht = blockIdx.x, c = blockIdx.y, b = blockIdx.z;
    const float* G = g_Gx + (((size_t)b * CC + c) * HH + ht * 128) * 64;
    const float* Fyb = g_Fy + (size_t)b * 64 * 512 + ht * 128;

    const int tid = threadIdx.x;
    const int tm = tid & 7, tn = tid >> 3;

    ull acc2[2][4];
#pragma unroll
    for (int i = 0; i < 2; i++)
#pragma unroll
        for (int q = 0; q < 4; q++) acc2[i][q] = 0ull;

    for (int hc = 0; hc < 128; hc += 32) {
        {
#pragma unroll
            for (int s = 0; s < 2; s++) {
                const int f4 = tid * 2 + s;
                const int h = f4 >> 4;
                const int m4 = (f4 & 15) * 4;
                *(float4*)&gxs[h][m4] = *(const float4*)&G[(hc + h) * 64 + m4];
            }
        }
        {
            const int n = tid >> 2;
            const int hh = (tid & 3) * 8;
            const float4 v0 = *(const float4*)&Fyb[n * 512 + hc + hh];
            const float4 v1 = *(const float4*)&Fyb[n * 512 + hc + hh + 4];
            *(float2*)&fyd[hh + 0][2 * n] = make_float2(v0.x, v0.x);
            *(float2*)&fyd[hh + 1][2 * n] = make_float2(v0.y, v0.y);
            *(float2*)&fyd[hh + 2][2 * n] = make_float2(v0.z, v0.z);
            *(float2*)&fyd[hh + 3][2 * n] = make_float2(v0.w, v0.w);
            *(float2*)&fyd[hh + 4][2 * n] = make_float2(v1.x, v1.x);
            *(float2*)&fyd[hh + 5][2 * n] = make_float2(v1.y, v1.y);
            *(float2*)&fyd[hh + 6][2 * n] = make_float2(v1.z, v1.z);
            *(float2*)&fyd[hh + 7][2 * n] = make_float2(v1.w, v1.w);
        }
        __syncthreads();

#pragma unroll 4
        for (int h = 0; h < 32; h++) {
            const ulonglong2 f = *(const ulonglong2*)&fyd[h][tn * 4];
            const ulonglong2 g0 = *(const ulonglong2*)&gxs[h][tm * 8];
            const ulonglong2 g1 = *(const ulonglong2*)&gxs[h][tm * 8 + 4];
            acc2[0][0] = fma2(f.x, g0.x, acc2[0][0]);
            acc2[0][1] = fma2(f.x, g0.y, acc2[0][1]);
            acc2[0][2] = fma2(f.x, g1.x, acc2[0][2]);
            acc2[0][3] = fma2(f.x, g1.y, acc2[0][3]);
            acc2[1][0] = fma2(f.y, g0.x, acc2[1][0]);
            acc2[1][1] = fma2(f.y, g0.y, acc2[1][1]);
            acc2[1][2] = fma2(f.y, g1.x, acc2[1][2]);
            acc2[1][3] = fma2(f.y, g1.y, acc2[1][3]);
        }
        __syncthreads();
    }

    float* O = g_outP[ht] + ((size_t)b * CC + c) * 4096;
#pragma unroll
    for (int i = 0; i < 2; i++) {
        const int n = tn * 2 + i;
        const float2 a0 = unpack2(acc2[i][0]);
        const float2 a1 = unpack2(acc2[i][1]);
        const float2 a2 = unpack2(acc2[i][2]);
        const float2 a3 = unpack2(acc2[i][3]);
        *(float4*)&O[n * 64 + tm * 8 + 0] = make_float4(a0.x, a0.y, a1.x, a1.y);
        *(float4*)&O[n * 64 + tm * 8 + 4] = make_float4(a2.x, a2.y, a3.x, a3.y);
    }
}

// K5: sum the 4 h-split partials
__global__ __launch_bounds__(256) void k_sumout(float* __restrict__ out) {
    const int i4 = (blockIdx.x * 256 + threadIdx.x) * 4;
    const float4 a = *(const float4*)&g_outP[0][i4];
    const float4 b = *(const float4*)&g_outP[1][i4];
    const float4 c = *(const float4*)&g_outP[2][i4];
    const float4 d = *(const float4*)&g_outP[3][i4];
    *(float4*)&out[i4] = make_float4(a.x + b.x + c.x + d.x, a.y + b.y + c.y + d.y,
                                     a.z + b.z + c.z + d.z, a.w + b.w + c.w + d.w);
}

// ============================================================================
extern "C" void kernel_launch(void* const* d_in, const int* in_sizes, int n_in,
                              void* d_out, int out_size) {
    (void)in_sizes; (void)n_in; (void)out_size;
    const float* X    = (const float*)d_in[0];
    const float* Wl   = (const float*)d_in[1];
    const float* bloc = (const float*)d_in[2];
    float* out = (float*)d_out;

    static int attr_set = 0;
    if (!attr_set) {
        cudaFuncSetAttribute(k_gemm1_mma,
                             cudaFuncAttributeMaxDynamicSharedMemorySize, GEMM1_DYN);
        attr_set = 1;
    }

    k_locnet<<<NBLK1, 256>>>(X, Wl);
    k_reduce_p<<<160, 32>>>(bloc);
    k_filters<<<dim3(64, 2, 32), 128>>>();
    k_gemm1_mma<<<dim3(4, 3, 32), 256, GEMM1_DYN>>>(X);
    k_gemm2<<<dim3(4, 3, 32), 256>>>();
    k_sumout<<<384, 256>>>(out);
}

// round 7
// speedup vs baseline: 2.9246x; 1.1551x over previous
#include <cuda_runtime.h>
#include <cuda_bf16.h>
#include <cstdint>

typedef unsigned long long ull;

// ---------------- problem constants ----------------
#define BB 32
#define CC 3
#define HH 512
#define WW 512
#define KTOT (CC*HH*WW)
#define NBLK1 384

// ---------------- device scratch ----------------
__device__ float g_partial[160 * NBLK1];
__device__ float g_p[BB * 5];
__device__ float g_Fx[BB * 64 * WW];
__device__ float g_Fy[BB * 64 * HH];
__device__ float g_Gx[BB * CC * HH * 64];
__device__ float g_outP[4][96 * 4096];

// ---------------- f32x2 helpers ----------------
__device__ __forceinline__ ull fma2(ull a, ull b, ull c) {
    ull d;
    asm("fma.rn.f32x2 %0, %1, %2, %3;" : "=l"(d) : "l"(a), "l"(b), "l"(c));
    return d;
}
__device__ __forceinline__ float2 unpack2(ull v) {
    float2 f;
    asm("mov.b64 {%0, %1}, %2;" : "=f"(f.x), "=f"(f.y) : "l"(v));
    return f;
}
__device__ __forceinline__ uint32_t smem_u32(const void* p) {
    uint32_t a;
    asm("{ .reg .u64 t; cvta.to.shared.u64 t, %1; cvt.u32.u64 %0, t; }" : "=r"(a) : "l"(p));
    return a;
}
#define SWZ(o) ((o) ^ (((o) >> 3) & 0x70))

__device__ __forceinline__ void ldsm_x4(uint32_t addr, uint32_t& r0, uint32_t& r1,
                                        uint32_t& r2, uint32_t& r3) {
    asm volatile("ldmatrix.sync.aligned.m8n8.x4.shared.b16 {%0,%1,%2,%3}, [%4];"
                 : "=r"(r0), "=r"(r1), "=r"(r2), "=r"(r3) : "r"(addr));
}
__device__ __forceinline__ void mma_bf16(float* c, const uint32_t* a, const uint32_t* b) {
    asm volatile(
        "mma.sync.aligned.m16n8k16.row.col.f32.bf16.bf16.f32 "
        "{%0,%1,%2,%3}, {%4,%5,%6,%7}, {%8,%9}, {%0,%1,%2,%3};"
        : "+f"(c[0]), "+f"(c[1]), "+f"(c[2]), "+f"(c[3])
        : "r"(a[0]), "r"(a[1]), "r"(a[2]), "r"(a[3]), "r"(b[0]), "r"(b[1]));
}
__device__ __forceinline__ void split4(float4 v, uint2& hv, uint2& lv) {
    __nv_bfloat16 h0 = __float2bfloat16_rn(v.x);
    __nv_bfloat16 h1 = __float2bfloat16_rn(v.y);
    __nv_bfloat16 h2 = __float2bfloat16_rn(v.z);
    __nv_bfloat16 h3 = __float2bfloat16_rn(v.w);
    __nv_bfloat16 l0 = __float2bfloat16_rn(v.x - __bfloat162float(h0));
    __nv_bfloat16 l1 = __float2bfloat16_rn(v.y - __bfloat162float(h1));
    __nv_bfloat16 l2 = __float2bfloat16_rn(v.z - __bfloat162float(h2));
    __nv_bfloat16 l3 = __float2bfloat16_rn(v.w - __bfloat162float(h3));
    hv.x = (uint32_t)__bfloat16_as_ushort(h0) | ((uint32_t)__bfloat16_as_ushort(h1) << 16);
    hv.y = (uint32_t)__bfloat16_as_ushort(h2) | ((uint32_t)__bfloat16_as_ushort(h3) << 16);
    lv.x = (uint32_t)__bfloat16_as_ushort(l0) | ((uint32_t)__bfloat16_as_ushort(l1) << 16);
    lv.y = (uint32_t)__bfloat16_as_ushort(l2) | ((uint32_t)__bfloat16_as_ushort(l3) << 16);
}

// ============================================================================
// K1: locnet (R4-proven, unchanged this round)
// ============================================================================
__global__ __launch_bounds__(256) void k_locnet(const float* __restrict__ X,
                                                const float* __restrict__ Wl) {
    __shared__ __align__(16) float Wt[5][2052];
    __shared__ float ps[160];
    const int tid = threadIdx.x;
    const int base = blockIdx.x * 2048;
    {
        const float* src = Wl + (size_t)base * 5;
#pragma unroll
        for (int it = 0; it < 10; it++) {
            const int e4 = tid * 4 + it * 1024;
            const float4 v = *(const float4*)&src[e4];
            const float vv[4] = {v.x, v.y, v.z, v.w};
#pragma unroll
            for (int r = 0; r < 4; r++) {
                const int e = e4 + r;
                Wt[e % 5][e / 5] = vv[r];
            }
        }
    }
    __syncthreads();
    const int lane = tid & 31, warp = tid >> 5;
    const int b0 = warp * 4;
    float acc[4][5];
#pragma unroll
    for (int bb = 0; bb < 4; bb++)
#pragma unroll
        for (int j = 0; j < 5; j++) acc[bb][j] = 0.0f;
#pragma unroll 4
    for (int qi = 0; qi < 16; qi++) {
        const int k = qi * 128 + lane * 4;
        float4 wv[5];
#pragma unroll
        for (int j = 0; j < 5; j++) wv[j] = *(const float4*)&Wt[j][k];
#pragma unroll
        for (int bb = 0; bb < 4; bb++) {
            const float4 x = *(const float4*)&X[(size_t)(b0 + bb) * KTOT + base + k];
#pragma unroll
            for (int j = 0; j < 5; j++) {
                acc[bb][j] = fmaf(x.x, wv[j].x, acc[bb][j]);
                acc[bb][j] = fmaf(x.y, wv[j].y, acc[bb][j]);
                acc[bb][j] = fmaf(x.z, wv[j].z, acc[bb][j]);
                acc[bb][j] = fmaf(x.w, wv[j].w, acc[bb][j]);
            }
        }
    }
#pragma unroll
    for (int bb = 0; bb < 4; bb++)
#pragma unroll
        for (int j = 0; j < 5; j++) {
            float v = acc[bb][j];
#pragma unroll
            for (int off = 16; off > 0; off >>= 1)
                v += __shfl_down_sync(0xffffffffu, v, off);
            if (lane == 0) ps[(b0 + bb) * 5 + j] = v;
        }
    __syncthreads();
    if (tid < 160) g_partial[tid * NBLK1 + blockIdx.x] = ps[tid];
}

__global__ __launch_bounds__(32) void k_reduce_p(const float* __restrict__ b_loc) {
    const int t = blockIdx.x, lane = threadIdx.x;
    const float* src = g_partial + (size_t)t * NBLK1;
    float s = 0.0f;
#pragma unroll
    for (int i = 0; i < NBLK1 / 32; i++) s += src[lane + i * 32];
#pragma unroll
    for (int off = 16; off > 0; off >>= 1)
        s += __shfl_down_sync(0xffffffffu, s, off);
    if (lane == 0) g_p[t] = s + b_loc[t % 5];
}

// ============================================================================
// K2: filter banks (unchanged)
// ============================================================================
__global__ __launch_bounds__(128) void k_filters() {
    const int n = blockIdx.x, axis = blockIdx.y, b = blockIdx.z;
    const int tid = threadIdx.x;
    const float* pb = g_p + b * 5;
    const float sigma2 = expf(pb[2]);
    const float delta = expf(pb[3]) * (511.0f / 63.0f);
    const float gctr = (axis == 0) ? 32.0f * (pb[0] + 1.0f) : 32.0f * (pb[1] + 1.0f);
    const float m = gctr + delta * ((float)n - 32.5f);
    const float inv2s = 1.0f / (2.0f * sigma2);
    float vals[4], lsum = 0.0f;
#pragma unroll
    for (int i = 0; i < 4; i++) {
        const float a = (float)(tid + i * 128);
        const float d = a - m;
        const float e = expf(-d * d * inv2s);
        vals[i] = e; lsum += e;
    }
    __shared__ float sw[4];
#pragma unroll
    for (int off = 16; off > 0; off >>= 1)
        lsum += __shfl_down_sync(0xffffffffu, lsum, off);
    if ((tid & 31) == 0) sw[tid >> 5] = lsum;
    __syncthreads();
    const float tot = sw[0] + sw[1] + sw[2] + sw[3];
    float scale = 1.0f / (tot + 1e-4f);
    if (axis == 1) scale *= expf(pb[4]);
    float* dst = (axis == 0 ? g_Fx : g_Fy) + ((size_t)b * 64 + n) * 512;
#pragma unroll
    for (int i = 0; i < 4; i++) dst[tid + i * 128] = vals[i] * scale;
}

// ============================================================================
// K3: GEMM1 mma.sync bf16 hi/lo with REGISTER-PREFETCH PIPELINE.
// Per chunk: prefetch next chunk's 12 LDG.128 into regs -> MMA current buffer
// -> convert regs into other buffer -> one __syncthreads.
// ============================================================================
#define PBUF 49152
#define GEMM1_DYN (2 * PBUF)

__global__ __launch_bounds__(256, 2) void k_gemm1_mma(const float* __restrict__ X) {
    extern __shared__ __align__(1024) char smem[];
    const uint32_t sbase = smem_u32(smem);

    const int tid = threadIdx.x;
    const int wid = tid >> 5, lane = tid & 31;
    const int ht = blockIdx.x, c = blockIdx.y, b = blockIdx.z;
    const int h0 = ht * 128;
    const float* Xbc = X + (((size_t)b * CC + c) * HH + h0) * WW;
    const float* Fxb = g_Fx + (size_t)b * 64 * 512;

    float acc[8][4];
#pragma unroll
    for (int nt = 0; nt < 8; nt++)
#pragma unroll
        for (int r = 0; r < 4; r++) acc[nt][r] = 0.0f;

    // load/store geometry
    const int xRow = tid >> 4;            // 0..15 (rows +p*16)
    const int xC4 = (tid & 15) * 4;       // 0..60
    const int fM = tid >> 2;              // 0..63
    const int fCb = (tid & 3) * 16;
    // ldmatrix geometry
    const int aRow = wid * 16 + (lane & 15);
    const int aK8 = (lane >> 4) * 8;
    const int bN = ((lane >> 4) << 3) + (lane & 7);
    const int bK8 = ((lane >> 3) & 1) * 8;

    float4 xr[8], fr[4];

#define LOADCH(w0)                                                              \
    do {                                                                        \
        _Pragma("unroll")                                                       \
        for (int p = 0; p < 8; p++)                                             \
            xr[p] = *(const float4*)&Xbc[(xRow + p * 16) * 512 + (w0) + xC4];   \
        _Pragma("unroll")                                                       \
        for (int q = 0; q < 4; q++)                                             \
            fr[q] = *(const float4*)&Fxb[fM * 512 + (w0) + fCb + q * 4];        \
    } while (0)

#define STORECH(bufP)                                                           \
    do {                                                                        \
        _Pragma("unroll")                                                       \
        for (int p = 0; p < 8; p++) {                                           \
            uint2 hv, lv;                                                       \
            split4(xr[p], hv, lv);                                              \
            const uint32_t so = SWZ((uint32_t)((xRow + p * 16) * 128 + xC4 * 2)); \
            *(uint2*)((bufP) + so) = hv;                                        \
            *(uint2*)((bufP) + 16384 + so) = lv;                                \
        }                                                                       \
        _Pragma("unroll")                                                       \
        for (int q = 0; q < 4; q++) {                                           \
            uint2 hv, lv;                                                       \
            split4(fr[q], hv, lv);                                              \
            const uint32_t so = SWZ((uint32_t)(fM * 128 + (fCb + q * 4) * 2));  \
            *(uint2*)((bufP) + 32768 + so) = hv;                                \
            *(uint2*)((bufP) + 40960 + so) = lv;                                \
        }                                                                       \
    } while (0)

    // prologue: fill buffer 0
    LOADCH(0);
    STORECH(smem);
    __syncthreads();

    for (int ch = 0; ch < 8; ch++) {
        const uint32_t bufU = sbase + (ch & 1) * PBUF;

        // prefetch next chunk into registers (LDG latency hides behind MMA)
        if (ch < 7) LOADCH((ch + 1) * 64);

        const uint32_t XH = bufU, XL = bufU + 16384;
        const uint32_t FH = bufU + 32768, FL = bufU + 40960;

#pragma unroll
        for (int kc = 0; kc < 64; kc += 16) {
            uint32_t ah[4], al[4];
            {
                const uint32_t off = SWZ((uint32_t)(aRow * 128 + (kc + aK8) * 2));
                ldsm_x4(XH + off, ah[0], ah[1], ah[2], ah[3]);
                ldsm_x4(XL + off, al[0], al[1], al[2], al[3]);
            }
#pragma unroll
            for (int half = 0; half < 2; half++) {
                uint32_t bh[8], bl[8];
#pragma unroll
                for (int nb = 0; nb < 2; nb++) {
                    const uint32_t off = SWZ(
                        (uint32_t)((bN + (half * 2 + nb) * 16) * 128 + (kc + bK8) * 2));
                    ldsm_x4(FH + off, bh[nb * 4 + 0], bh[nb * 4 + 1],
                            bh[nb * 4 + 2], bh[nb * 4 + 3]);
                    ldsm_x4(FL + off, bl[nb * 4 + 0], bl[nb * 4 + 1],
                            bl[nb * 4 + 2], bl[nb * 4 + 3]);
                }
#pragma unroll
                for (int nt = 0; nt < 4; nt++) {
                    float* a = acc[half * 4 + nt];
                    mma_bf16(a, ah, &bh[nt * 2]);   // hi*hi
                    mma_bf16(a, ah, &bl[nt * 2]);   // hi*lo
                    mma_bf16(a, al, &bh[nt * 2]);   // lo*hi
                }
            }
        }

        // convert prefetched regs into the other buffer
        if (ch < 7) {
            char* nb = smem + ((ch + 1) & 1) * PBUF;
            STORECH(nb);
        }
        __syncthreads();
    }

    float* G = g_Gx + (((size_t)b * CC + c) * HH + h0) * 64;
    const int r0 = wid * 16 + (lane >> 2);
    const int c0 = (lane & 3) * 2;
#pragma unroll
    for (int nt = 0; nt < 8; nt++) {
        *(float2*)&G[(r0 + 0) * 64 + nt * 8 + c0] = make_float2(acc[nt][0], acc[nt][1]);
        *(float2*)&G[(r0 + 8) * 64 + nt * 8 + c0] = make_float2(acc[nt][2], acc[nt][3]);
    }
#undef LOADCH
#undef STORECH
}

// ============================================================================
// K4: partial out over h-range of 128. grid (4 ht, 3 c, 32 b), 256 thr.
// ============================================================================
__global__ __launch_bounds__(256) void k_gemm2() {
    __shared__ __align__(16) float gxs[32][68];
    __shared__ __align__(16) float fyd[32][132];

    const int ht = blockIdx.x, c = blockIdx.y, b = blockIdx.z;
    const float* G = g_Gx + (((size_t)b * CC + c) * HH + ht * 128) * 64;
    const float* Fyb = g_Fy + (size_t)b * 64 * 512 + ht * 128;

    const int tid = threadIdx.x;
    const int tm = tid & 7, tn = tid >> 3;

    ull acc2[2][4];
#pragma unroll
    for (int i = 0; i < 2; i++)
#pragma unroll
        for (int q = 0; q < 4; q++) acc2[i][q] = 0ull;

    for (int hc = 0; hc < 128; hc += 32) {
        {
#pragma unroll
            for (int s = 0; s < 2; s++) {
                const int f4 = tid * 2 + s;
                const int h = f4 >> 4;
                const int m4 = (f4 & 15) * 4;
                *(float4*)&gxs[h][m4] = *(const float4*)&G[(hc + h) * 64 + m4];
            }
        }
        {
            const int n = tid >> 2;
            const int hh = (tid & 3) * 8;
            const float4 v0 = *(const float4*)&Fyb[n * 512 + hc + hh];
            const float4 v1 = *(const float4*)&Fyb[n * 512 + hc + hh + 4];
            *(float2*)&fyd[hh + 0][2 * n] = make_float2(v0.x, v0.x);
            *(float2*)&fyd[hh + 1][2 * n] = make_float2(v0.y, v0.y);
            *(float2*)&fyd[hh + 2][2 * n] = make_float2(v0.z, v0.z);
            *(float2*)&fyd[hh + 3][2 * n] = make_float2(v0.w, v0.w);
            *(float2*)&fyd[hh + 4][2 * n] = make_float2(v1.x, v1.x);
            *(float2*)&fyd[hh + 5][2 * n] = make_float2(v1.y, v1.y);
            *(float2*)&fyd[hh + 6][2 * n] = make_float2(v1.z, v1.z);
            *(float2*)&fyd[hh + 7][2 * n] = make_float2(v1.w, v1.w);
        }
        __syncthreads();

#pragma unroll 4
        for (int h = 0; h < 32; h++) {
            const ulonglong2 f = *(const ulonglong2*)&fyd[h][tn * 4];
            const ulonglong2 g0 = *(const ulonglong2*)&gxs[h][tm * 8];
            const ulonglong2 g1 = *(const ulonglong2*)&gxs[h][tm * 8 + 4];
            acc2[0][0] = fma2(f.x, g0.x, acc2[0][0]);
            acc2[0][1] = fma2(f.x, g0.y, acc2[0][1]);
            acc2[0][2] = fma2(f.x, g1.x, acc2[0][2]);
            acc2[0][3] = fma2(f.x, g1.y, acc2[0][3]);
            acc2[1][0] = fma2(f.y, g0.x, acc2[1][0]);
            acc2[1][1] = fma2(f.y, g0.y, acc2[1][1]);
            acc2[1][2] = fma2(f.y, g1.x, acc2[1][2]);
            acc2[1][3] = fma2(f.y, g1.y, acc2[1][3]);
        }
        __syncthreads();
    }

    float* O = g_outP[ht] + ((size_t)b * CC + c) * 4096;
#pragma unroll
    for (int i = 0; i < 2; i++) {
        const int n = tn * 2 + i;
        const float2 a0 = unpack2(acc2[i][0]);
        const float2 a1 = unpack2(acc2[i][1]);
        const float2 a2 = unpack2(acc2[i][2]);
        const float2 a3 = unpack2(acc2[i][3]);
        *(float4*)&O[n * 64 + tm * 8 + 0] = make_float4(a0.x, a0.y, a1.x, a1.y);
        *(float4*)&O[n * 64 + tm * 8 + 4] = make_float4(a2.x, a2.y, a3.x, a3.y);
    }
}

// K5: sum the 4 h-split partials
__global__ __launch_bounds__(256) void k_sumout(float* __restrict__ out) {
    const int i4 = (blockIdx.x * 256 + threadIdx.x) * 4;
    const float4 a = *(const float4*)&g_outP[0][i4];
    const float4 b = *(const float4*)&g_outP[1][i4];
    const float4 c = *(const float4*)&g_outP[2][i4];
    const float4 d = *(const float4*)&g_outP[3][i4];
    *(float4*)&out[i4] = make_float4(a.x + b.x + c.x + d.x, a.y + b.y + c.y + d.y,
                                     a.z + b.z + c.z + d.z, a.w + b.w + c.w + d.w);
}

// ============================================================================
extern "C" void kernel_launch(void* const* d_in, const int* in_sizes, int n_in,
                              void* d_out, int out_size) {
    (void)in_sizes; (void)n_in; (void)out_size;
    const float* X    = (const float*)d_in[0];
    const float* Wl   = (const float*)d_in[1];
    const float* bloc = (const float*)d_in[2];
    float* out = (float*)d_out;

    static int attr_set = 0;
    if (!attr_set) {
        cudaFuncSetAttribute(k_gemm1_mma,
                             cudaFuncAttributeMaxDynamicSharedMemorySize, GEMM1_DYN);
        attr_set = 1;
    }

    k_locnet<<<NBLK1, 256>>>(X, Wl);
    k_reduce_p<<<160, 32>>>(bloc);
    k_filters<<<dim3(64, 2, 32), 128>>>();
    k_gemm1_mma<<<dim3(4, 3, 32), 256, GEMM1_DYN>>>(X);
    k_gemm2<<<dim3(4, 3, 32), 256>>>();
    k_sumout<<<384, 256>>>(out);
}